// round 6
// baseline (speedup 1.0000x reference)
#include <cuda_runtime.h>
#include <cuda_bf16.h>
#include <cstdint>

// out[b,a,f] = (a < M[b]) * relu( resid[b,a,:] @ w[:,f] + node[b,a,f] )
// B=4096, A=128, K=RF=128, F=128 fp32.
// Tensor path via mma.sync m16n8k16 bf16 (available on compute_103 — tcgen05 is
// 'a'-gated and the harness emits compute_103 PTX).
// 3-pass split: D = Ah*Bh + Al*Bh + Ah*Bl, fp32 register accumulators.

#define A_DIM 128
#define F_DIM 128
#define K_DIM 128
#define TROWS 64

// smem byte offsets: A frag tiles [4 mb][8 ks][32 lane][16B], B [8 ks][16 nb][32 lane][8B]
#define SM_AH 0
#define SM_AL 16384
#define SM_BH 32768
#define SM_BL 65536
#define SMEM_TOTAL 98304

__device__ __forceinline__ uint32_t smem_u32(const void* p) {
    uint32_t a;
    asm("{ .reg .u64 t; cvta.to.shared.u64 t, %1; cvt.u32.u64 %0, t; }" : "=r"(a) : "l"(p));
    return a;
}

__device__ __forceinline__ uint32_t pack2(__nv_bfloat16 a, __nv_bfloat16 b) {
    __nv_bfloat162 p(a, b);           // a -> low 16 bits (even k), b -> high
    return *(uint32_t*)&p;
}

__device__ __forceinline__ void split2(float x, __nv_bfloat16& h, __nv_bfloat16& l) {
    h = __float2bfloat16(x);
    l = __float2bfloat16(x - __bfloat162float(h));
}

#define LDS128(r0, r1, r2, r3, addr) \
    asm volatile("ld.shared.v4.b32 {%0,%1,%2,%3}, [%4];" \
                 : "=r"(r0), "=r"(r1), "=r"(r2), "=r"(r3) : "r"(addr))
#define LDS64(r0, r1, addr) \
    asm volatile("ld.shared.v2.b32 {%0,%1}, [%2];" : "=r"(r0), "=r"(r1) : "r"(addr))

__device__ __forceinline__ void mma_bf16(float* c, const uint32_t* a,
                                         uint32_t b0, uint32_t b1) {
    asm volatile(
        "mma.sync.aligned.m16n8k16.row.col.f32.bf16.bf16.f32 "
        "{%0,%1,%2,%3}, {%4,%5,%6,%7}, {%8,%9}, {%0,%1,%2,%3};"
        : "+f"(c[0]), "+f"(c[1]), "+f"(c[2]), "+f"(c[3])
        : "r"(a[0]), "r"(a[1]), "r"(a[2]), "r"(a[3]), "r"(b0), "r"(b1));
}

__global__ __launch_bounds__(128, 2)
void blockend_mma(const float* __restrict__ node,
                  const float* __restrict__ resid,
                  const float* __restrict__ w,
                  const int*   __restrict__ mol_i32,
                  float* __restrict__ out,
                  int B)
{
    extern __shared__ char sm[];
    const uint32_t smb = smem_u32(sm);
    const int t    = threadIdx.x;
    const int wid  = t >> 5;
    const int lane = t & 31;
    const int wr   = wid >> 1;     // warp row group: local rows wr*32 .. wr*32+31
    const int wc   = wid & 1;      // warp col group: cols wc*64 .. wc*64+63

    // mol_slice layout: int64 -> i32 view [M,0,128,0,...] ; int32 -> [M,128,...]
    const bool is_i64 = (mol_i32[1] == 0);

    // ---- one-time: stage w split into fragment-order Bh/Bl ----
    // B frag (m16n8k16, col): elem (k,n): lane=(n&7)*4+((k&7)>>1), reg=(k>>3)&1, slot=k&1
    {
        const float4* wsrc = (const float4*)w;
        #pragma unroll 4
        for (int i = 0; i < 32; i++) {
            int idx4 = t + (i << 7);
            int k  = idx4 >> 5;
            int n0 = (idx4 & 31) << 2;
            float4 v = wsrc[idx4];
            float xs[4] = {v.x, v.y, v.z, v.w};
            int ks = k >> 4;
            int rs = (((k >> 3) & 1) << 2) + ((k & 1) << 1);  // reg*4 + slot*2
            int kl = (k & 7) >> 1;
            #pragma unroll
            for (int j = 0; j < 4; j++) {
                int n = n0 + j;
                __nv_bfloat16 h, l;
                split2(xs[j], h, l);
                int off = (((ks << 4) + (n >> 3)) << 8) + ((((n & 7) << 2) + kl) << 3) + rs;
                *(__nv_bfloat16*)(sm + SM_BH + off) = h;
                *(__nv_bfloat16*)(sm + SM_BL + off) = l;
            }
        }
    }
    __syncthreads();

    const int total = B * 2;
    for (int tile = blockIdx.x; tile < total; tile += gridDim.x) {
        const int b    = tile >> 1;
        const int row0 = (tile & 1) << 6;
        const int M    = is_i64 ? mol_i32[4 * b] : mol_i32[2 * b];
        float* otile = out + ((size_t)b * A_DIM + row0) * F_DIM;

        // ---- fully masked tile: zero fill ----
        if (row0 >= M) {
            float4 z = make_float4(0.f, 0.f, 0.f, 0.f);
            float4* o4 = (float4*)otile;
            #pragma unroll
            for (int i = 0; i < 16; i++) o4[t + (i << 7)] = z;
            continue;
        }

        __syncthreads();   // previous tile's compute done before smem A overwrite

        // ---- stage resid tile split into fragment-order Ah/Al ----
        // A frag: elem (r,k): lane=(r&7)*4+((k&7)>>1), reg=((r>>3)&1)+2*((k>>3)&1)
        // reg position rotated by ks to de-conflict STS banks.
        {
            const float4* rsrc = (const float4*)(resid + ((size_t)b * A_DIM + row0) * K_DIM);
            #pragma unroll
            for (int i = 0; i < 16; i++) {
                int idx4 = t + (i << 7);
                int r = idx4 >> 5;                  // local row, warp-uniform
                if (row0 + r < M) {
                    int k4 = (idx4 & 31) << 2;
                    float4 v = rsrc[idx4];
                    int mb = r >> 4;
                    int ks = k4 >> 4;
                    int reg = ((r >> 3) & 1) + (((k4 >> 3) & 1) << 1);
                    int lane_s = ((r & 7) << 2) + ((k4 & 7) >> 1);
                    int off = (((mb << 3) + ks) << 9) + (lane_s << 4)
                            + (((reg + ks) & 3) << 2);
                    __nv_bfloat16 h0, l0, h1, l1, h2, l2, h3, l3;
                    split2(v.x, h0, l0); split2(v.y, h1, l1);
                    split2(v.z, h2, l2); split2(v.w, h3, l3);
                    *(uint32_t*)(sm + SM_AH + off)      = pack2(h0, h1);
                    *(uint32_t*)(sm + SM_AL + off)      = pack2(l0, l1);
                    *(uint32_t*)(sm + SM_AH + off + 16) = pack2(h2, h3);   // k4+2: lane_s+1
                    *(uint32_t*)(sm + SM_AL + off + 16) = pack2(l2, l3);
                }
            }
        }
        __syncthreads();

        // ---- compute: per-warp 32x64 C tile, 3-pass bf16 split ----
        const int  mbg0 = wr << 1;
        const bool act0 = row0 + (mbg0 << 4) < M;
        const bool act1 = row0 + ((mbg0 + 1) << 4) < M;

        float c[2][8][4];
        #pragma unroll
        for (int mb = 0; mb < 2; mb++)
            #pragma unroll
            for (int nb = 0; nb < 8; nb++)
                #pragma unroll
                for (int i = 0; i < 4; i++) c[mb][nb][i] = 0.f;

        if (act0) {
            const uint32_t abase0 = smb + ((mbg0 << 3) << 9) + (lane << 4);
            const uint32_t abase1 = smb + (((mbg0 + 1) << 3) << 9) + (lane << 4);
            const uint32_t bbase  = smb + SM_BH + ((wc << 3) << 8) + (lane << 3);

            #pragma unroll
            for (int ks = 0; ks < 8; ks++) {
                uint32_t t0[4], t1[4], t2[4], t3[4];
                uint32_t ah0[4], al0[4], ah1[4], al1[4];
                LDS128(t0[0], t0[1], t0[2], t0[3], abase0 + SM_AH + (ks << 9));
                LDS128(t1[0], t1[1], t1[2], t1[3], abase0 + SM_AL + (ks << 9));
                if (act1) {
                    LDS128(t2[0], t2[1], t2[2], t2[3], abase1 + SM_AH + (ks << 9));
                    LDS128(t3[0], t3[1], t3[2], t3[3], abase1 + SM_AL + (ks << 9));
                }
                #pragma unroll
                for (int i = 0; i < 4; i++) {
                    ah0[i] = t0[(i + ks) & 3];
                    al0[i] = t1[(i + ks) & 3];
                    ah1[i] = t2[(i + ks) & 3];
                    al1[i] = t3[(i + ks) & 3];
                }
                #pragma unroll
                for (int nb = 0; nb < 8; nb++) {
                    uint32_t boff = bbase + (((ks << 4) + nb) << 8);
                    uint32_t bh0, bh1, bl0, bl1;
                    LDS64(bh0, bh1, boff);
                    LDS64(bl0, bl1, boff + (SM_BL - SM_BH));
                    mma_bf16(c[0][nb], ah0, bh0, bh1);
                    mma_bf16(c[0][nb], al0, bh0, bh1);
                    mma_bf16(c[0][nb], ah0, bl0, bl1);
                    if (act1) {
                        mma_bf16(c[1][nb], ah1, bh0, bh1);
                        mma_bf16(c[1][nb], al1, bh0, bh1);
                        mma_bf16(c[1][nb], ah1, bl0, bl1);
                    }
                }
            }
        }

        // ---- epilogue: + node, relu, row mask, store (covers all 64x128) ----
        const float* nt = node + ((size_t)b * A_DIM + row0) * F_DIM;
        #pragma unroll
        for (int mb = 0; mb < 2; mb++) {
            int rb = ((mbg0 + mb) << 4) + (lane >> 2);
            #pragma unroll
            for (int half = 0; half < 2; half++) {
                int r = rb + (half << 3);
                bool on = (row0 + r) < M;
                int ci = half << 1;
                #pragma unroll
                for (int nb = 0; nb < 8; nb++) {
                    int col = (wc << 6) + (nb << 3) + ((lane & 3) << 1);
                    float2 o;
                    if (on) {
                        float2 nv = *(const float2*)(nt + r * F_DIM + col);
                        o.x = fmaxf(c[mb][nb][ci]     + nv.x, 0.f);
                        o.y = fmaxf(c[mb][nb][ci + 1] + nv.y, 0.f);
                    } else {
                        o.x = 0.f; o.y = 0.f;
                    }
                    *(float2*)(otile + r * F_DIM + col) = o;
                }
            }
        }
    }
}

extern "C" void kernel_launch(void* const* d_in, const int* in_sizes, int n_in,
                              void* d_out, int out_size) {
    // size-based input identification (robust to metadata ordering)
    const float* node = nullptr;
    const float* res  = nullptr;
    const void*  wptr = nullptr;
    const void*  mptr = nullptr;

    for (int i = 0; i < n_in; i++) {
        if (in_sizes[i] >= (1 << 20)) {
            if (!node) node = (const float*)d_in[i];
            else if (!res) res = (const float*)d_in[i];
        }
    }
    for (int i = 0; i < n_in; i++) {
        if (in_sizes[i] < (1 << 20)) {
            if (!wptr && in_sizes[i] == F_DIM * K_DIM) { wptr = d_in[i]; continue; }
            if (!mptr && d_in[i] != wptr) mptr = d_in[i];
        }
    }
    if (!node) node = (const float*)d_in[0];
    if (!res)  res  = (const float*)d_in[1];
    if (!wptr) wptr = d_in[2];
    if (!mptr) mptr = d_in[3];

    int B = 0;
    for (int i = 0; i < n_in; i++)
        if (in_sizes[i] >= (1 << 20)) { B = in_sizes[i] / (A_DIM * F_DIM); break; }
    if (!B) B = 4096;

    int dev = 0, sms = 148;
    cudaGetDevice(&dev);
    cudaDeviceGetAttribute(&sms, cudaDevAttrMultiProcessorCount, dev);
    cudaFuncSetAttribute(blockend_mma, cudaFuncAttributeMaxDynamicSharedMemorySize,
                         SMEM_TOTAL);

    int grid = 2 * sms;
    if (grid > 2 * B) grid = 2 * B;
    blockend_mma<<<grid, 128, SMEM_TOTAL>>>(node, res, (const float*)wptr,
                                            (const int*)mptr, (float*)d_out, B);
}

// round 7
// speedup vs baseline: 2.1057x; 2.1057x over previous
#include <cuda_runtime.h>
#include <cuda_bf16.h>
#include <cstdint>

// out[b,a,f] = (a < M[b]) * relu( resid[b,a,:] @ w[:,f] + node[b,a,f] )
// B=4096, A=128, K=RF=128, F=128 fp32.
// mma.sync m16n8k16 bf16, 3-pass split D = Ah*Bh + Al*Bh + Ah*Bl (fp32 accum).
// Persistent, 512 thr/CTA, cp.async double-staged raw resid tile.

#define A_DIM 128
#define F_DIM 128
#define K_DIM 128

// smem: raw fp32 A (64K) | Ah (32K) | Al (32K) | Bh (32K) | Bl (32K) = 192 KB
#define SM_RAW 0
#define SM_AH  65536
#define SM_AL  98304
#define SM_BH  131072
#define SM_BL  163840
#define SMEM_TOTAL 196608

__device__ __forceinline__ uint32_t smem_u32(const void* p) {
    uint32_t a;
    asm("{ .reg .u64 t; cvta.to.shared.u64 t, %1; cvt.u32.u64 %0, t; }" : "=r"(a) : "l"(p));
    return a;
}
__device__ __forceinline__ uint32_t pack2(__nv_bfloat16 a, __nv_bfloat16 b) {
    __nv_bfloat162 p(a, b);
    return *(uint32_t*)&p;
}
__device__ __forceinline__ void split2(float x, __nv_bfloat16& h, __nv_bfloat16& l) {
    h = __float2bfloat16(x);
    l = __float2bfloat16(x - __bfloat162float(h));
}

#define LDS128(r0, r1, r2, r3, addr) \
    asm volatile("ld.shared.v4.b32 {%0,%1,%2,%3}, [%4];" \
                 : "=r"(r0), "=r"(r1), "=r"(r2), "=r"(r3) : "r"(addr))
#define LDS64(r0, r1, addr) \
    asm volatile("ld.shared.v2.b32 {%0,%1}, [%2];" : "=r"(r0), "=r"(r1) : "r"(addr))
#define CP_ASYNC16(dst, src) \
    asm volatile("cp.async.cg.shared.global [%0], [%1], 16;" :: "r"(dst), "l"(src))
#define CP_COMMIT() asm volatile("cp.async.commit_group;" ::: "memory")
#define CP_WAIT0()  asm volatile("cp.async.wait_group 0;" ::: "memory")

__device__ __forceinline__ void mma_bf16(float* c, const uint32_t* a,
                                         uint32_t b0, uint32_t b1) {
    asm volatile(
        "mma.sync.aligned.m16n8k16.row.col.f32.bf16.bf16.f32 "
        "{%0,%1,%2,%3}, {%4,%5,%6,%7}, {%8,%9}, {%0,%1,%2,%3};"
        : "+f"(c[0]), "+f"(c[1]), "+f"(c[2]), "+f"(c[3])
        : "r"(a[0]), "r"(a[1]), "r"(a[2]), "r"(a[3]), "r"(b0), "r"(b1));
}

__global__ __launch_bounds__(512, 1)
void blockend_mma(const float* __restrict__ node,
                  const float* __restrict__ resid,
                  const float* __restrict__ w,
                  const int*   __restrict__ mol_i32,
                  float* __restrict__ out,
                  int B)
{
    extern __shared__ char sm[];
    const uint32_t smb = smem_u32(sm);
    const int t    = threadIdx.x;
    const int wid  = t >> 5;
    const int lane = t & 31;
    const int mb   = wid >> 1;     // warp m-block: rows mb*16 .. mb*16+15
    const int wc   = wid & 1;      // warp col half: cols wc*64 .. wc*64+63

    const bool is_i64 = (mol_i32[1] == 0);

    // ---- prologue: kick off cp.async for first molecule ----
    int b0 = blockIdx.x;
    int M_cur = 0;
    if (b0 < B) {
        M_cur = is_i64 ? mol_i32[4 * b0] : mol_i32[2 * b0];
        const char* src = (const char*)(resid + (size_t)b0 * A_DIM * K_DIM);
        #pragma unroll
        for (int i = 0; i < 8; i++) {
            int idx = t + (i << 9);            // 0..4095 16B chunks
            int r   = idx >> 5;                // row (warp-uniform)
            if (r < M_cur)
                CP_ASYNC16(smb + SM_RAW + (idx << 4), src + ((size_t)idx << 4));
        }
        CP_COMMIT();
    }

    // ---- one-time: stage w split into fragment-order Bh/Bl ----
    // B frag (m16n8k16 col): elem (k,n): lane=(n&7)*4+((k&7)>>1), reg=(k>>3)&1, slot=k&1
    {
        const float4* wsrc = (const float4*)w;
        #pragma unroll
        for (int i = 0; i < 8; i++) {
            int idx4 = t + (i << 9);
            int k  = idx4 >> 5;
            int n0 = (idx4 & 31) << 2;
            float4 v = wsrc[idx4];
            float xs[4] = {v.x, v.y, v.z, v.w};
            int ks = k >> 4;
            int rs = (((k >> 3) & 1) << 2) + ((k & 1) << 1);
            int kl = (k & 7) >> 1;
            #pragma unroll
            for (int j = 0; j < 4; j++) {
                int n = n0 + j;
                __nv_bfloat16 h, l;
                split2(xs[j], h, l);
                int off = (((ks << 4) + (n >> 3)) << 8) + ((((n & 7) << 2) + kl) << 3) + rs;
                *(__nv_bfloat16*)(sm + SM_BH + off) = h;
                *(__nv_bfloat16*)(sm + SM_BL + off) = l;
            }
        }
    }

    for (int b = b0; b < B; b += gridDim.x) {
        const int M = M_cur;

        // ---- raw tile ready; also guarantees previous iter's frag reads done ----
        CP_WAIT0();
        __syncthreads();

        // ---- convert raw fp32 -> fragment-order Ah/Al (rows < M only) ----
        // A frag: elem (r,k): lane=(r&7)*4+((k&7)>>1), reg=((r>>3)&1)+2*((k>>3)&1)
        // reg slot rotated by ks to de-conflict STS banks.  (validated R6 layout)
        #pragma unroll
        for (int i = 0; i < 8; i++) {
            int idx4 = t + (i << 9);
            int r = idx4 >> 5;                 // warp-uniform
            if (r < M) {
                int k4 = (idx4 & 31) << 2;
                uint32_t u0, u1, u2, u3;
                LDS128(u0, u1, u2, u3, smb + SM_RAW + (idx4 << 4));
                float4 v;
                v.x = __uint_as_float(u0); v.y = __uint_as_float(u1);
                v.z = __uint_as_float(u2); v.w = __uint_as_float(u3);
                int amb = r >> 4;
                int ks  = k4 >> 4;
                int reg = ((r >> 3) & 1) + (((k4 >> 3) & 1) << 1);
                int lane_s = ((r & 7) << 2) + ((k4 & 7) >> 1);
                int off = (((amb << 3) + ks) << 9) + (lane_s << 4)
                        + (((reg + ks) & 3) << 2);
                __nv_bfloat16 h0, l0, h1, l1, h2, l2, h3, l3;
                split2(v.x, h0, l0); split2(v.y, h1, l1);
                split2(v.z, h2, l2); split2(v.w, h3, l3);
                *(uint32_t*)(sm + SM_AH + off)      = pack2(h0, h1);
                *(uint32_t*)(sm + SM_AL + off)      = pack2(l0, l1);
                *(uint32_t*)(sm + SM_AH + off + 16) = pack2(h2, h3);
                *(uint32_t*)(sm + SM_AL + off + 16) = pack2(l2, l3);
            }
        }
        __syncthreads();   // frags ready; raw now free for next tile

        // ---- kick off cp.async for next molecule (overlaps compute) ----
        const int bn = b + gridDim.x;
        if (bn < B) {
            M_cur = is_i64 ? mol_i32[4 * bn] : mol_i32[2 * bn];
            const char* src = (const char*)(resid + (size_t)bn * A_DIM * K_DIM);
            #pragma unroll
            for (int i = 0; i < 8; i++) {
                int idx = t + (i << 9);
                int r   = idx >> 5;
                if (r < M_cur)
                    CP_ASYNC16(smb + SM_RAW + (idx << 4), src + ((size_t)idx << 4));
            }
            CP_COMMIT();
        }

        // ---- compute: warp = 16 rows x 64 cols, 3-pass bf16 split ----
        const bool act = (mb << 4) < M;
        float c[8][4];
        #pragma unroll
        for (int nb = 0; nb < 8; nb++)
            #pragma unroll
            for (int i = 0; i < 4; i++) c[nb][i] = 0.f;

        if (act) {
            const uint32_t abase = smb + ((mb << 3) << 9) + (lane << 4);
            const uint32_t bbase = smb + SM_BH + (lane << 3);
            #pragma unroll
            for (int ks = 0; ks < 8; ks++) {
                uint32_t t0[4], t1[4], ah[4], al[4];
                LDS128(t0[0], t0[1], t0[2], t0[3], abase + SM_AH + (ks << 9));
                LDS128(t1[0], t1[1], t1[2], t1[3], abase + SM_AL + (ks << 9));
                #pragma unroll
                for (int i = 0; i < 4; i++) {
                    ah[i] = t0[(i + ks) & 3];
                    al[i] = t1[(i + ks) & 3];
                }
                #pragma unroll
                for (int nb = 0; nb < 8; nb++) {
                    uint32_t boff = bbase + (((ks << 4) + (wc << 3) + nb) << 8);
                    uint32_t bh0, bh1, bl0, bl1;
                    LDS64(bh0, bh1, boff);
                    LDS64(bl0, bl1, boff + (SM_BL - SM_BH));
                    mma_bf16(c[nb], ah, bh0, bh1);
                    mma_bf16(c[nb], al, bh0, bh1);
                    mma_bf16(c[nb], ah, bl0, bl1);
                }
            }
        }

        // ---- epilogue: + node, relu, row mask, store ----
        const float* nt = node + (size_t)b * A_DIM * F_DIM;
        float*       ot = out  + (size_t)b * A_DIM * F_DIM;
        const int rbase = (mb << 4) + (lane >> 2);
        const int cbase = (wc << 6) + ((lane & 3) << 1);
        #pragma unroll
        for (int half = 0; half < 2; half++) {
            int r  = rbase + (half << 3);
            bool on = r < M;
            int ci = half << 1;
            #pragma unroll
            for (int nb = 0; nb < 8; nb++) {
                int col = cbase + (nb << 3);
                float2 o;
                if (on) {
                    float2 nv = *(const float2*)(nt + r * F_DIM + col);
                    o.x = fmaxf(c[nb][ci]     + nv.x, 0.f);
                    o.y = fmaxf(c[nb][ci + 1] + nv.y, 0.f);
                } else {
                    o.x = 0.f; o.y = 0.f;
                }
                *(float2*)(ot + r * F_DIM + col) = o;
            }
        }
    }
}

extern "C" void kernel_launch(void* const* d_in, const int* in_sizes, int n_in,
                              void* d_out, int out_size) {
    // size-based input identification (robust to metadata ordering)
    const float* node = nullptr;
    const float* res  = nullptr;
    const void*  wptr = nullptr;
    const void*  mptr = nullptr;

    for (int i = 0; i < n_in; i++) {
        if (in_sizes[i] >= (1 << 20)) {
            if (!node) node = (const float*)d_in[i];
            else if (!res) res = (const float*)d_in[i];
        }
    }
    for (int i = 0; i < n_in; i++) {
        if (in_sizes[i] < (1 << 20)) {
            if (!wptr && in_sizes[i] == F_DIM * K_DIM) { wptr = d_in[i]; continue; }
            if (!mptr && d_in[i] != wptr) mptr = d_in[i];
        }
    }
    if (!node) node = (const float*)d_in[0];
    if (!res)  res  = (const float*)d_in[1];
    if (!wptr) wptr = d_in[2];
    if (!mptr) mptr = d_in[3];

    int B = 0;
    for (int i = 0; i < n_in; i++)
        if (in_sizes[i] >= (1 << 20)) { B = in_sizes[i] / (A_DIM * F_DIM); break; }
    if (!B) B = 4096;

    int dev = 0, sms = 148;
    cudaGetDevice(&dev);
    cudaDeviceGetAttribute(&sms, cudaDevAttrMultiProcessorCount, dev);
    cudaFuncSetAttribute(blockend_mma, cudaFuncAttributeMaxDynamicSharedMemorySize,
                         SMEM_TOTAL);

    int grid = sms < B ? sms : B;
    blockend_mma<<<grid, 512, SMEM_TOTAL>>>(node, res, (const float*)wptr,
                                            (const int*)mptr, (float*)d_out, B);
}

// round 8
// speedup vs baseline: 2.2275x; 1.0578x over previous
#include <cuda_runtime.h>
#include <cuda_bf16.h>
#include <cstdint>

// out[b,a,f] = (a < M[b]) * relu( resid[b,a,:] @ w[:,f] + node[b,a,f] )
// B=4096, A=128, K=RF=128, F=128 fp32.
// mma.sync m16n8k16 bf16, 3-pass split D = Ah*Bh + Al*Bh + Ah*Bl (fp32 accum).
// A: direct LDG->split->mma (no staging). node: double-buffered cp.async smem.

#define A_DIM 128
#define F_DIM 128
#define K_DIM 128

// smem: node buf0 (128 rows x 528B) | node buf1 | Bh (40960) | Bl (40960)
#define NPITCH 528
#define SM_N0  0
#define SM_N1  67584
#define SM_BH  135168
#define SM_BL  176128
#define SMEM_TOTAL 217088

__device__ __forceinline__ uint32_t smem_u32(const void* p) {
    uint32_t a;
    asm("{ .reg .u64 t; cvta.to.shared.u64 t, %1; cvt.u32.u64 %0, t; }" : "=r"(a) : "l"(p));
    return a;
}
__device__ __forceinline__ uint32_t pack2h(float x, float y) {
    __nv_bfloat162 p(__float2bfloat16(x), __float2bfloat16(y));
    return *(uint32_t*)&p;
}
__device__ __forceinline__ uint32_t pack2l(float x, float y) {
    __nv_bfloat16 hx = __float2bfloat16(x), hy = __float2bfloat16(y);
    __nv_bfloat162 p(__float2bfloat16(x - __bfloat162float(hx)),
                     __float2bfloat16(y - __bfloat162float(hy)));
    return *(uint32_t*)&p;
}

#define LDS128(r0, r1, r2, r3, addr) \
    asm volatile("ld.shared.v4.b32 {%0,%1,%2,%3}, [%4];" \
                 : "=r"(r0), "=r"(r1), "=r"(r2), "=r"(r3) : "r"(addr))
#define CP_ASYNC16(dst, src) \
    asm volatile("cp.async.cg.shared.global [%0], [%1], 16;" :: "r"(dst), "l"(src))
#define CP_COMMIT() asm volatile("cp.async.commit_group;" ::: "memory")
#define CP_WAIT1()  asm volatile("cp.async.wait_group 1;" ::: "memory")

__device__ __forceinline__ void mma_bf16(float* c, const uint32_t* a,
                                         uint32_t b0, uint32_t b1) {
    asm volatile(
        "mma.sync.aligned.m16n8k16.row.col.f32.bf16.bf16.f32 "
        "{%0,%1,%2,%3}, {%4,%5,%6,%7}, {%8,%9}, {%0,%1,%2,%3};"
        : "+f"(c[0]), "+f"(c[1]), "+f"(c[2]), "+f"(c[3])
        : "r"(a[0]), "r"(a[1]), "r"(a[2]), "r"(a[3]), "r"(b0), "r"(b1));
}

__global__ __launch_bounds__(512, 1)
void blockend_mma(const float* __restrict__ node,
                  const float* __restrict__ resid,
                  const float* __restrict__ w,
                  const int*   __restrict__ mol_i32,
                  float* __restrict__ out,
                  int B)
{
    extern __shared__ char sm[];
    const uint32_t smb = smem_u32(sm);
    const int t    = threadIdx.x;
    const int wid  = t >> 5;
    const int lane = t & 31;
    const int mb   = wid >> 1;     // warp m-block: rows mb*16 .. +15
    const int wc   = wid & 1;      // warp col half: cols wc*64 .. +63

    const bool is_i64 = (mol_i32[1] == 0);

    // ---- prologue: cp.async node(first tile) into buf0 ----
    int p = 0;
    const int b0 = blockIdx.x;
    int M_cur = is_i64 ? mol_i32[4 * b0] : mol_i32[2 * b0];
    {
        const char* src = (const char*)(node + (size_t)b0 * A_DIM * F_DIM);
        #pragma unroll
        for (int i = 0; i < 8; i++) {
            int idx = t + (i << 9);            // 16B chunk id, 0..4095
            int r   = idx >> 5;                // row (warp-uniform)
            if (r < M_cur)
                CP_ASYNC16(smb + SM_N0 + r * NPITCH + ((idx & 31) << 4),
                           src + ((size_t)idx << 4));
        }
        CP_COMMIT();
    }

    // ---- one-time: w split into padded fragment layout Bh/Bl ----
    // element (k,n): ks=k>>4, wc=n>>6, nbl=(n>>3)&7, lane=(n&7)*4+((k&7)>>1),
    //   off = ((ks*2+wc)*32+lane)*80 + (nbl*2+((k>>3)&1))*4 + (k&1)*2
    {
        const float4* wsrc = (const float4*)w;
        #pragma unroll
        for (int i = 0; i < 8; i++) {
            int idx4 = t + (i << 9);
            int k  = idx4 >> 5;
            int n0 = (idx4 & 31) << 2;
            float4 v = wsrc[idx4];
            float xs[4] = {v.x, v.y, v.z, v.w};
            int ks  = k >> 4;
            int rs  = ((((k >> 3) & 1)) << 2) + ((k & 1) << 1);
            int kl  = (k & 7) >> 1;
            #pragma unroll
            for (int j = 0; j < 4; j++) {
                int n   = n0 + j;
                int ln  = ((n & 7) << 2) + kl;
                int off = (((ks << 1) + (n >> 6)) * 32 + ln) * 80
                        + (((n >> 3) & 7) << 3) + rs;
                float x = xs[j];
                __nv_bfloat16 h = __float2bfloat16(x);
                *(__nv_bfloat16*)(sm + SM_BH + off) = h;
                *(__nv_bfloat16*)(sm + SM_BL + off) =
                    __float2bfloat16(x - __bfloat162float(h));
            }
        }
    }
    __syncthreads();

    for (int b = b0; b < B; b += gridDim.x) {
        const int M = M_cur;

        // ---- issue cp.async node(next tile) into buf[p^1] ----
        const int bn = b + gridDim.x;
        int M_nxt = 0;
        if (bn < B) {
            M_nxt = is_i64 ? mol_i32[4 * bn] : mol_i32[2 * bn];
            const uint32_t dbase = smb + (p ? SM_N0 : SM_N1);
            const char* src = (const char*)(node + (size_t)bn * A_DIM * F_DIM);
            #pragma unroll
            for (int i = 0; i < 8; i++) {
                int idx = t + (i << 9);
                int r   = idx >> 5;
                if (r < M_nxt)
                    CP_ASYNC16(dbase + r * NPITCH + ((idx & 31) << 4),
                               src + ((size_t)idx << 4));
            }
        }
        CP_COMMIT();   // always commit (keeps wait_group accounting correct)

        // ---- compute: warp = 16 rows x 64 cols, A direct from gmem ----
        const bool act = (mb << 4) < M;
        float c[8][4];
        #pragma unroll
        for (int nb = 0; nb < 8; nb++)
            #pragma unroll
            for (int i = 0; i < 4; i++) c[nb][i] = 0.f;

        if (act) {
            const int R0  = (mb << 4) + (lane >> 2);
            const int kl2 = (lane & 3) << 1;
            const float* r0p = resid + ((size_t)b * A_DIM + R0) * K_DIM + kl2;
            const float* r1p = r0p + 8 * K_DIM;
            const uint32_t bbase = smb + SM_BH + (uint32_t)((wc << 5) + lane) * 80;

            float2 cur[4], nxt[4];
            cur[0] = *(const float2*)(r0p);          // (R0,   k,k+1)
            cur[1] = *(const float2*)(r0p + 8);      // (R0,   k+8,k+9)
            cur[2] = *(const float2*)(r1p);          // (R0+8, k,k+1)
            cur[3] = *(const float2*)(r1p + 8);      // (R0+8, k+8,k+9)

            #pragma unroll
            for (int ks = 0; ks < 8; ks++) {
                if (ks < 7) {
                    int kb = (ks + 1) << 4;
                    nxt[0] = *(const float2*)(r0p + kb);
                    nxt[1] = *(const float2*)(r0p + kb + 8);
                    nxt[2] = *(const float2*)(r1p + kb);
                    nxt[3] = *(const float2*)(r1p + kb + 8);
                }
                // a-frag order: a0=(r,k) a1=(r+8,k) a2=(r,k+8) a3=(r+8,k+8)
                uint32_t ah[4], al[4];
                ah[0] = pack2h(cur[0].x, cur[0].y);
                ah[1] = pack2h(cur[2].x, cur[2].y);
                ah[2] = pack2h(cur[1].x, cur[1].y);
                ah[3] = pack2h(cur[3].x, cur[3].y);
                al[0] = pack2l(cur[0].x, cur[0].y);
                al[1] = pack2l(cur[2].x, cur[2].y);
                al[2] = pack2l(cur[1].x, cur[1].y);
                al[3] = pack2l(cur[3].x, cur[3].y);

                const uint32_t ba = bbase + (uint32_t)(ks << 1) * 32 * 80;
                uint32_t h0[4], h1[4], h2[4], h3[4];
                uint32_t l0[4], l1[4], l2[4], l3[4];
                LDS128(h0[0], h0[1], h0[2], h0[3], ba);
                LDS128(h1[0], h1[1], h1[2], h1[3], ba + 16);
                LDS128(h2[0], h2[1], h2[2], h2[3], ba + 32);
                LDS128(h3[0], h3[1], h3[2], h3[3], ba + 48);
                LDS128(l0[0], l0[1], l0[2], l0[3], ba + (SM_BL - SM_BH));
                LDS128(l1[0], l1[1], l1[2], l1[3], ba + (SM_BL - SM_BH) + 16);
                LDS128(l2[0], l2[1], l2[2], l2[3], ba + (SM_BL - SM_BH) + 32);
                LDS128(l3[0], l3[1], l3[2], l3[3], ba + (SM_BL - SM_BH) + 48);

                mma_bf16(c[0], ah, h0[0], h0[1]);
                mma_bf16(c[0], al, h0[0], h0[1]);
                mma_bf16(c[0], ah, l0[0], l0[1]);
                mma_bf16(c[1], ah, h0[2], h0[3]);
                mma_bf16(c[1], al, h0[2], h0[3]);
                mma_bf16(c[1], ah, l0[2], l0[3]);
                mma_bf16(c[2], ah, h1[0], h1[1]);
                mma_bf16(c[2], al, h1[0], h1[1]);
                mma_bf16(c[2], ah, l1[0], l1[1]);
                mma_bf16(c[3], ah, h1[2], h1[3]);
                mma_bf16(c[3], al, h1[2], h1[3]);
                mma_bf16(c[3], ah, l1[2], l1[3]);
                mma_bf16(c[4], ah, h2[0], h2[1]);
                mma_bf16(c[4], al, h2[0], h2[1]);
                mma_bf16(c[4], ah, l2[0], l2[1]);
                mma_bf16(c[5], ah, h2[2], h2[3]);
                mma_bf16(c[5], al, h2[2], h2[3]);
                mma_bf16(c[5], ah, l2[2], l2[3]);
                mma_bf16(c[6], ah, h3[0], h3[1]);
                mma_bf16(c[6], al, h3[0], h3[1]);
                mma_bf16(c[6], ah, l3[0], l3[1]);
                mma_bf16(c[7], ah, h3[2], h3[3]);
                mma_bf16(c[7], al, h3[2], h3[3]);
                mma_bf16(c[7], ah, l3[2], l3[3]);

                cur[0] = nxt[0]; cur[1] = nxt[1];
                cur[2] = nxt[2]; cur[3] = nxt[3];
            }
        }

        // ---- node(t) arrived; epilogue from smem ----
        CP_WAIT1();
        __syncthreads();

        const char* nbuf = sm + (p ? SM_N1 : SM_N0);
        float* ot = out + (size_t)b * A_DIM * F_DIM;
        const int rbase = (mb << 4) + (lane >> 2);
        const int cbase = (wc << 6) + ((lane & 3) << 1);
        #pragma unroll
        for (int half = 0; half < 2; half++) {
            int r  = rbase + (half << 3);
            bool on = r < M;
            int ci = half << 1;
            #pragma unroll
            for (int nb = 0; nb < 8; nb++) {
                int col = cbase + (nb << 3);
                float2 o;
                if (on) {
                    float2 nv = *(const float2*)(nbuf + r * NPITCH + (col << 2));
                    o.x = fmaxf(c[nb][ci]     + nv.x, 0.f);
                    o.y = fmaxf(c[nb][ci + 1] + nv.y, 0.f);
                } else {
                    o.x = 0.f; o.y = 0.f;
                }
                *(float2*)(ot + r * F_DIM + col) = o;
            }
        }
        __syncthreads();   // epilogue reads done before buf[p] is overwritten next iter

        p ^= 1;
        M_cur = M_nxt;
    }
}

extern "C" void kernel_launch(void* const* d_in, const int* in_sizes, int n_in,
                              void* d_out, int out_size) {
    // size-based input identification (robust to metadata ordering)
    const float* node = nullptr;
    const float* res  = nullptr;
    const void*  wptr = nullptr;
    const void*  mptr = nullptr;

    for (int i = 0; i < n_in; i++) {
        if (in_sizes[i] >= (1 << 20)) {
            if (!node) node = (const float*)d_in[i];
            else if (!res) res = (const float*)d_in[i];
        }
    }
    for (int i = 0; i < n_in; i++) {
        if (in_sizes[i] < (1 << 20)) {
            if (!wptr && in_sizes[i] == F_DIM * K_DIM) { wptr = d_in[i]; continue; }
            if (!mptr && d_in[i] != wptr) mptr = d_in[i];
        }
    }
    if (!node) node = (const float*)d_in[0];
    if (!res)  res  = (const float*)d_in[1];
    if (!wptr) wptr = d_in[2];
    if (!mptr) mptr = d_in[3];

    int B = 0;
    for (int i = 0; i < n_in; i++)
        if (in_sizes[i] >= (1 << 20)) { B = in_sizes[i] / (A_DIM * F_DIM); break; }
    if (!B) B = 4096;

    int dev = 0, sms = 148;
    cudaGetDevice(&dev);
    cudaDeviceGetAttribute(&sms, cudaDevAttrMultiProcessorCount, dev);
    cudaFuncSetAttribute(blockend_mma, cudaFuncAttributeMaxDynamicSharedMemorySize,
                         SMEM_TOTAL);

    int grid = sms < B ? sms : B;
    blockend_mma<<<grid, 512, SMEM_TOTAL>>>(node, res, (const float*)wptr,
                                            (const int*)mptr, (float*)d_out, B);
}

// round 10
// speedup vs baseline: 2.4286x; 1.0903x over previous
#include <cuda_runtime.h>
#include <cuda_bf16.h>
#include <cstdint>

// out[b,a,f] = (a < M[b]) * relu( resid[b,a,:] @ w[:,f] + node[b,a,f] )
// B=4096, A=128, K=RF=128, F=128 fp32.
// mma.sync m16n8k16 bf16, 3-pass split D = Ah*Bh + Al*Bh + Ah*Bl (fp32 accum).
// resid: double-buffered cp.async raw tile (pitch 560B). node: direct LDG epilogue.

#define A_DIM 128
#define F_DIM 128
#define K_DIM 128

#define RPITCH 560                 // 140 floats: row bank-starts all distinct
#define SM_R0  0
#define SM_R1  71680               // 128*560
#define SM_BH  143360
#define SM_BL  184320
#define SMEM_TOTAL 225280

__device__ __forceinline__ uint32_t smem_u32(const void* p) {
    uint32_t a;
    asm("{ .reg .u64 t; cvta.to.shared.u64 t, %1; cvt.u32.u64 %0, t; }" : "=r"(a) : "l"(p));
    return a;
}
__device__ __forceinline__ uint32_t pack2h(float x, float y) {
    __nv_bfloat162 p(__float2bfloat16(x), __float2bfloat16(y));
    return *(uint32_t*)&p;
}
__device__ __forceinline__ uint32_t pack2l(float x, float y) {
    __nv_bfloat16 hx = __float2bfloat16(x), hy = __float2bfloat16(y);
    __nv_bfloat162 p(__float2bfloat16(x - __bfloat162float(hx)),
                     __float2bfloat16(y - __bfloat162float(hy)));
    return *(uint32_t*)&p;
}

#define LDS128(r0, r1, r2, r3, addr) \
    asm volatile("ld.shared.v4.b32 {%0,%1,%2,%3}, [%4];" \
                 : "=r"(r0), "=r"(r1), "=r"(r2), "=r"(r3) : "r"(addr))
#define LDS64F(f0, f1, addr) \
    asm volatile("ld.shared.v2.f32 {%0,%1}, [%2];" : "=f"(f0), "=f"(f1) : "r"(addr))
#define CP_ASYNC16(dst, src) \
    asm volatile("cp.async.cg.shared.global [%0], [%1], 16;" :: "r"(dst), "l"(src))
#define CP_COMMIT() asm volatile("cp.async.commit_group;" ::: "memory")
#define CP_WAIT1()  asm volatile("cp.async.wait_group 1;" ::: "memory")

__device__ __forceinline__ void mma_bf16(float* c, const uint32_t* a,
                                         uint32_t b0, uint32_t b1) {
    asm volatile(
        "mma.sync.aligned.m16n8k16.row.col.f32.bf16.bf16.f32 "
        "{%0,%1,%2,%3}, {%4,%5,%6,%7}, {%8,%9}, {%0,%1,%2,%3};"
        : "+f"(c[0]), "+f"(c[1]), "+f"(c[2]), "+f"(c[3])
        : "r"(a[0]), "r"(a[1]), "r"(a[2]), "r"(a[3]), "r"(b0), "r"(b1));
}

__global__ __launch_bounds__(512, 1)
void blockend_mma(const float* __restrict__ node,
                  const float* __restrict__ resid,
                  const float* __restrict__ w,
                  const int*   __restrict__ mol_i32,
                  float* __restrict__ out,
                  int B)
{
    extern __shared__ char sm[];
    const uint32_t smb = smem_u32(sm);
    const int t    = threadIdx.x;
    const int wid  = t >> 5;
    const int lane = t & 31;
    const int mb   = wid >> 1;     // warp m-block: rows mb*16 .. +15
    const int wc   = wid & 1;      // warp col half: cols wc*64 .. +63

    const bool is_i64 = (mol_i32[1] == 0);

    // ---- prologue: cp.async resid(first tile) into buf0 ----
    int p = 0;
    const int b0 = blockIdx.x;
    int M_cur = 0;
    if (b0 < B) {
        M_cur = is_i64 ? mol_i32[4 * b0] : mol_i32[2 * b0];
        const char* src = (const char*)(resid + (size_t)b0 * A_DIM * K_DIM);
        #pragma unroll
        for (int i = 0; i < 8; i++) {
            int idx = t + (i << 9);            // 16B chunk id, 0..4095
            int r   = idx >> 5;                // row (warp-uniform)
            if (r < M_cur)
                CP_ASYNC16(smb + SM_R0 + r * RPITCH + ((idx & 31) << 4),
                           src + ((size_t)idx << 4));
        }
        CP_COMMIT();
    }

    // ---- one-time: w split into padded fragment layout Bh/Bl (validated R8) ----
    {
        const float4* wsrc = (const float4*)w;
        #pragma unroll
        for (int i = 0; i < 8; i++) {
            int idx4 = t + (i << 9);
            int k  = idx4 >> 5;
            int n0 = (idx4 & 31) << 2;
            float4 v = wsrc[idx4];
            float xs[4] = {v.x, v.y, v.z, v.w};
            int ks  = k >> 4;
            int rs  = ((((k >> 3) & 1)) << 2) + ((k & 1) << 1);
            int kl  = (k & 7) >> 1;
            #pragma unroll
            for (int j = 0; j < 4; j++) {
                int n   = n0 + j;
                int ln  = ((n & 7) << 2) + kl;
                int off = (((ks << 1) + (n >> 6)) * 32 + ln) * 80
                        + (((n >> 3) & 7) << 3) + rs;
                float x = xs[j];
                __nv_bfloat16 h = __float2bfloat16(x);
                *(__nv_bfloat16*)(sm + SM_BH + off) = h;
                *(__nv_bfloat16*)(sm + SM_BL + off) =
                    __float2bfloat16(x - __bfloat162float(h));
            }
        }
    }

    for (int b = b0; b < B; b += gridDim.x) {
        const int M = M_cur;

        // ---- issue cp.async resid(next tile) into buf[p^1] ----
        const int bn = b + gridDim.x;
        int M_nxt = 0;
        if (bn < B) {
            M_nxt = is_i64 ? mol_i32[4 * bn] : mol_i32[2 * bn];
            const uint32_t dbase = smb + (p ? SM_R0 : SM_R1);
            const char* src = (const char*)(resid + (size_t)bn * A_DIM * K_DIM);
            #pragma unroll
            for (int i = 0; i < 8; i++) {
                int idx = t + (i << 9);
                int r   = idx >> 5;
                if (r < M_nxt)
                    CP_ASYNC16(dbase + r * RPITCH + ((idx & 31) << 4),
                               src + ((size_t)idx << 4));
            }
        }
        CP_COMMIT();               // always commit: keeps group accounting uniform

        CP_WAIT1();                // resid(t) arrived (groups complete in order)
        __syncthreads();

        // ---- compute: warp = 16 rows x 64 cols, A from smem raw buf ----
        const bool act = (mb << 4) < M;
        float c[8][4];
        #pragma unroll
        for (int nb = 0; nb < 8; nb++)
            #pragma unroll
            for (int i = 0; i < 4; i++) c[nb][i] = 0.f;

        if (act) {
            const int R0  = (mb << 4) + (lane >> 2);
            const uint32_t abase = smb + (p ? SM_R1 : SM_R0)
                                 + (uint32_t)R0 * RPITCH + (((uint32_t)lane & 3) << 3);
            const uint32_t bbase = smb + SM_BH + (uint32_t)((wc << 5) + lane) * 80;

            #pragma unroll
            for (int ks = 0; ks < 8; ks++) {
                // A: rows R0, R0+8 ; k = kl2 + 16ks and +8
                float a00x, a00y, a01x, a01y, a10x, a10y, a11x, a11y;
                const uint32_t ak = abase + ((uint32_t)ks << 6);
                LDS64F(a00x, a00y, ak);                       // (R0,   k)
                LDS64F(a01x, a01y, ak + 32);                  // (R0,   k+8)
                LDS64F(a10x, a10y, ak + 8 * RPITCH);          // (R0+8, k)
                LDS64F(a11x, a11y, ak + 8 * RPITCH + 32);     // (R0+8, k+8)

                // a-frag order: a0=(r,k) a1=(r+8,k) a2=(r,k+8) a3=(r+8,k+8)
                uint32_t ah[4], al[4];
                ah[0] = pack2h(a00x, a00y);
                ah[1] = pack2h(a10x, a10y);
                ah[2] = pack2h(a01x, a01y);
                ah[3] = pack2h(a11x, a11y);
                al[0] = pack2l(a00x, a00y);
                al[1] = pack2l(a10x, a10y);
                al[2] = pack2l(a01x, a01y);
                al[3] = pack2l(a11x, a11y);

                const uint32_t ba = bbase + (uint32_t)(ks << 1) * 32 * 80;
                uint32_t h0[4], h1[4], h2[4], h3[4];
                uint32_t l0[4], l1[4], l2[4], l3[4];
                LDS128(h0[0], h0[1], h0[2], h0[3], ba);
                LDS128(h1[0], h1[1], h1[2], h1[3], ba + 16);
                LDS128(h2[0], h2[1], h2[2], h2[3], ba + 32);
                LDS128(h3[0], h3[1], h3[2], h3[3], ba + 48);
                LDS128(l0[0], l0[1], l0[2], l0[3], ba + (SM_BL - SM_BH));
                LDS128(l1[0], l1[1], l1[2], l1[3], ba + (SM_BL - SM_BH) + 16);
                LDS128(l2[0], l2[1], l2[2], l2[3], ba + (SM_BL - SM_BH) + 32);
                LDS128(l3[0], l3[1], l3[2], l3[3], ba + (SM_BL - SM_BH) + 48);

                mma_bf16(c[0], ah, h0[0], h0[1]);
                mma_bf16(c[0], al, h0[0], h0[1]);
                mma_bf16(c[0], ah, l0[0], l0[1]);
                mma_bf16(c[1], ah, h0[2], h0[3]);
                mma_bf16(c[1], al, h0[2], h0[3]);
                mma_bf16(c[1], ah, l0[2], l0[3]);
                mma_bf16(c[2], ah, h1[0], h1[1]);
                mma_bf16(c[2], al, h1[0], h1[1]);
                mma_bf16(c[2], ah, l1[0], l1[1]);
                mma_bf16(c[3], ah, h1[2], h1[3]);
                mma_bf16(c[3], al, h1[2], h1[3]);
                mma_bf16(c[3], ah, l1[2], l1[3]);
                mma_bf16(c[4], ah, h2[0], h2[1]);
                mma_bf16(c[4], al, h2[0], h2[1]);
                mma_bf16(c[4], ah, l2[0], l2[1]);
                mma_bf16(c[5], ah, h2[2], h2[3]);
                mma_bf16(c[5], al, h2[2], h2[3]);
                mma_bf16(c[5], ah, l2[2], l2[3]);
                mma_bf16(c[6], ah, h3[0], h3[1]);
                mma_bf16(c[6], al, h3[0], h3[1]);
                mma_bf16(c[6], ah, l3[0], l3[1]);
                mma_bf16(c[7], ah, h3[2], h3[3]);
                mma_bf16(c[7], al, h3[2], h3[3]);
                mma_bf16(c[7], ah, l3[2], l3[3]);
            }
        }

        // ---- epilogue: + node (direct LDG), relu, row mask, store ----
        const float* nt = node + (size_t)b * A_DIM * F_DIM;
        float*       ot = out  + (size_t)b * A_DIM * F_DIM;
        const int rbase = (mb << 4) + (lane >> 2);
        const int cbase = (wc << 6) + ((lane & 3) << 1);
        #pragma unroll
        for (int half = 0; half < 2; half++) {
            int r  = rbase + (half << 3);
            bool on = r < M;
            int ci = half << 1;
            #pragma unroll
            for (int nb = 0; nb < 8; nb++) {
                int col = cbase + (nb << 3);
                float2 o;
                if (on) {
                    float2 nv = *(const float2*)(nt + r * F_DIM + col);
                    o.x = fmaxf(c[nb][ci]     + nv.x, 0.f);
                    o.y = fmaxf(c[nb][ci + 1] + nv.y, 0.f);
                } else {
                    o.x = 0.f; o.y = 0.f;
                }
                *(float2*)(ot + r * F_DIM + col) = o;
            }
        }
        __syncthreads();   // compute reads of buf[p] done before next overwrite

        p ^= 1;
        M_cur = M_nxt;
    }
}

extern "C" void kernel_launch(void* const* d_in, const int* in_sizes, int n_in,
                              void* d_out, int out_size) {
    // size-based input identification (robust to metadata ordering)
    const float* node = nullptr;
    const float* res  = nullptr;
    const void*  wptr = nullptr;
    const void*  mptr = nullptr;

    for (int i = 0; i < n_in; i++) {
        if (in_sizes[i] >= (1 << 20)) {
            if (!node) node = (const float*)d_in[i];
            else if (!res) res = (const float*)d_in[i];
        }
    }
    for (int i = 0; i < n_in; i++) {
        if (in_sizes[i] < (1 << 20)) {
            if (!wptr && in_sizes[i] == F_DIM * K_DIM) { wptr = d_in[i]; continue; }
            if (!mptr && d_in[i] != wptr) mptr = d_in[i];
        }
    }
    if (!node) node = (const float*)d_in[0];
    if (!res)  res  = (const float*)d_in[1];
    if (!wptr) wptr = d_in[2];
    if (!mptr) mptr = d_in[3];

    int B = 0;
    for (int i = 0; i < n_in; i++)
        if (in_sizes[i] >= (1 << 20)) { B = in_sizes[i] / (A_DIM * F_DIM); break; }
    if (!B) B = 4096;

    int dev = 0, sms = 148;
    cudaGetDevice(&dev);
    cudaDeviceGetAttribute(&sms, cudaDevAttrMultiProcessorCount, dev);
    cudaFuncSetAttribute(blockend_mma, cudaFuncAttributeMaxDynamicSharedMemorySize,
                         SMEM_TOTAL);

    int grid = sms < B ? sms : B;
    blockend_mma<<<grid, 512, SMEM_TOTAL>>>(node, res, (const float*)wptr,
                                            (const int*)mptr, (float*)d_out, B);
}